// round 7
// baseline (speedup 1.0000x reference)
#include <cuda_runtime.h>

#define B 32
#define H 512
#define W 512
#define WPR 16                   // 512 bits / 32 = 16 words per row
#define STRIP 32                 // rows per warp (stats)
#define GX (H / STRIP)           // 16 stats row-blocks per batch

#define MBAND 128                // medial interior rows per CTA
#define MNB (H / MBAND)          // 4 bands
#define MWARPS 6                 // 4 interior + 2 halo warps
#define MTHREADS (MWARPS * 32)   // 192
#define MEDIAL_BLOCKS (MNB * B * 2)

// ---- device scratch (no allocations allowed) ----
__device__ unsigned g_pmask[B * H * WPR];
__device__ unsigned g_gmask[B * H * WPR];
__device__ float    g_part[GX][B][12];   // per-CTA stats partials (race-free)
__device__ int      g_mds [B][2][MNB];
__device__ int      g_mcnt[B][2][MNB];
__device__ int      g_done = 0;          // last-block counter (self-resetting)

// ======================= stats =======================
struct Raw { float4 v; float eL, eR; };

__device__ __forceinline__ Raw load_raw(const float* __restrict__ rowptr,
                                        int lane, int x0, bool ok) {
    Raw r;
    if (ok) {
        r.v  = *(const float4*)rowptr;
        r.eL = (lane == 0  && x0 > 0)     ? __ldg(rowptr - 1) : 0.f;
        r.eR = (lane == 31 && x0 + 4 < W) ? __ldg(rowptr + 4) : 0.f;
    } else {
        r.v = make_float4(0.f, 0.f, 0.f, 0.f);
        r.eL = r.eR = 0.f;
    }
    return r;
}

struct RowH { float p[4]; float h[4]; };

__device__ __forceinline__ RowH convert(const Raw& r, int lane) {
    float Lp = __shfl_up_sync(0xffffffffu, r.v.w, 1);
    float Rp = __shfl_down_sync(0xffffffffu, r.v.x, 1);
    if (lane == 0)  Lp = r.eL;
    if (lane == 31) Rp = r.eR;
    RowH o;
    o.p[0] = r.v.x; o.p[1] = r.v.y; o.p[2] = r.v.z; o.p[3] = r.v.w;
    o.h[0] = Lp + r.v.x + r.v.y;
    o.h[1] = r.v.x + r.v.y + r.v.z;
    o.h[2] = r.v.y + r.v.z + r.v.w;
    o.h[3] = r.v.z + r.v.w + Rp;
    return o;
}

// grid (GX, B), block 128 = 4 warps; 3-row raw prefetch pipeline (6 loads in flight).
__global__ void __launch_bounds__(128) stats_kernel(const float* __restrict__ pred,
                                                    const float* __restrict__ gt) {
    const int lane = threadIdx.x & 31;
    const int cs   = threadIdx.x >> 5;
    const int b    = blockIdx.y;
    const int y0   = blockIdx.x * STRIP;
    const int x0   = cs * 128 + lane * 4;

    const float* Pp = pred + (size_t)b * H * W + x0 + (size_t)(y0 - 1) * W;
    const float* Gp = gt   + (size_t)b * H * W + x0 + (size_t)(y0 - 1) * W;

    Raw rp = load_raw(Pp, lane, x0, y0 > 0);
    Raw rg = load_raw(Gp, lane, x0, y0 > 0);
    Pp += W; Gp += W;
    Raw rp0 = load_raw(Pp, lane, x0, true);
    Raw rg0 = load_raw(Gp, lane, x0, true);
    Pp += W; Gp += W;
    Raw vP1 = load_raw(Pp, lane, x0, y0 + 1 < H);
    Raw vG1 = load_raw(Gp, lane, x0, y0 + 1 < H);
    Pp += W; Gp += W;
    Raw vP2 = load_raw(Pp, lane, x0, y0 + 2 < H);
    Raw vG2 = load_raw(Gp, lane, x0, y0 + 2 < H);
    Pp += W; Gp += W;
    Raw vP3 = load_raw(Pp, lane, x0, y0 + 3 < H);
    Raw vG3 = load_raw(Gp, lane, x0, y0 + 3 < H);
    Pp += W; Gp += W;

    RowH ppr = convert(rp, lane);
    RowH gpr = convert(rg, lane);
    float pph[4] = { ppr.h[0], ppr.h[1], ppr.h[2], ppr.h[3] };
    float gph[4] = { gpr.h[0], gpr.h[1], gpr.h[2], gpr.h[3] };
    RowH pc = convert(rp0, lane);
    RowH gc = convert(rg0, lane);

    float a_i = 0.f, a_p = 0.f, a_g = 0.f;
    int c[9] = {0, 0, 0, 0, 0, 0, 0, 0, 0};

    #pragma unroll 4
    for (int j = 0; j < STRIP; j++) {
        const int y = y0 + j;
        // issue loads for row y+4 (consumed three iterations later)
        Raw vPn = load_raw(Pp, lane, x0, y + 4 < H);
        Raw vGn = load_raw(Gp, lane, x0, y + 4 < H);
        Pp += W; Gp += W;

        RowH pnx = convert(vP1, lane);   // row y+1
        RowH gnx = convert(vG1, lane);

        unsigned pnib = 0, gnib = 0;
        #pragma unroll
        for (int i = 0; i < 4; i++) {
            float pv = pc.p[i], gv = gc.p[i];
            float pn = pph[i] + pc.h[i] + pnx.h[i] - pv;
            float gn = gph[i] + gc.h[i] + gnx.h[i] - gv;
            bool pon = pv > 0.5f, gon = gv > 0.5f;
            int pe = pon && (pn == 1.f), pm = pon && (pn == 2.f), pj = pon && (pn > 2.f);
            int ge = gon && (gn == 1.f), gm = gon && (gn == 2.f), gj = gon && (gn > 2.f);
            a_i += pv * gv; a_p += pv; a_g += gv;
            c[0] += pe; c[1] += ge; c[2] += (pe & ge);
            c[3] += pm; c[4] += gm; c[5] += (pm & gm);
            c[6] += pj; c[7] += gj; c[8] += (pj & gj);
            pnib |= (unsigned)pon << i;
            gnib |= (unsigned)gon << i;
        }

        unsigned pw = pnib << ((lane & 7) * 4);
        unsigned gw = gnib << ((lane & 7) * 4);
        pw |= __shfl_xor_sync(0xffffffffu, pw, 1);
        gw |= __shfl_xor_sync(0xffffffffu, gw, 1);
        pw |= __shfl_xor_sync(0xffffffffu, pw, 2);
        gw |= __shfl_xor_sync(0xffffffffu, gw, 2);
        pw |= __shfl_xor_sync(0xffffffffu, pw, 4);
        gw |= __shfl_xor_sync(0xffffffffu, gw, 4);
        if ((lane & 7) == 0) {
            size_t widx = (size_t)(b * H + y) * WPR + cs * 4 + (lane >> 3);
            g_pmask[widx] = pw;
            g_gmask[widx] = gw;
        }

        #pragma unroll
        for (int i = 0; i < 4; i++) { pph[i] = pc.h[i]; gph[i] = gc.h[i]; }
        pc = pnx; gc = gnx;
        vP1 = vP2; vG1 = vG2;
        vP2 = vP3; vG2 = vG3;
        vP3 = vPn; vG3 = vGn;
    }

    #pragma unroll
    for (int o = 16; o; o >>= 1) {
        a_i += __shfl_down_sync(0xffffffffu, a_i, o);
        a_p += __shfl_down_sync(0xffffffffu, a_p, o);
        a_g += __shfl_down_sync(0xffffffffu, a_g, o);
    }
    #pragma unroll
    for (int k = 0; k < 9; k++) {
        #pragma unroll
        for (int o = 16; o; o >>= 1) c[k] += __shfl_down_sync(0xffffffffu, c[k], o);
    }

    __shared__ float sf[3];
    __shared__ int   si[9];
    if (threadIdx.x < 3) sf[threadIdx.x] = 0.f;
    if (threadIdx.x < 9) si[threadIdx.x] = 0;
    __syncthreads();
    if (lane == 0) {
        atomicAdd(&sf[0], a_i); atomicAdd(&sf[1], a_p); atomicAdd(&sf[2], a_g);
        #pragma unroll
        for (int k = 0; k < 9; k++) atomicAdd(&si[k], c[k]);
    }
    __syncthreads();
    if (threadIdx.x < 3)  g_part[blockIdx.x][b][threadIdx.x] = sf[threadIdx.x];
    if (threadIdx.x >= 3 && threadIdx.x < 12)
        g_part[blockIdx.x][b][threadIdx.x] = (float)si[threadIdx.x - 3];
}

// ======================= medial: register-resident rows =======================
// grid (MNB, B*2), block 192 = 6 warps (warps 0 and 5 are vertical halo).
// Lane = row; 16 words/lane. 9 rounds. Shrinking uncovered-set accumulator:
//   dist_sum = popc(tgt) + sum_{d=1..9} popc(unc_d),  unc_d = unc_{d-1} & ~dil_d
__global__ void __launch_bounds__(MTHREADS, 2) medial_kernel(float* __restrict__ out) {
    const int lane = threadIdx.x & 31;
    const int w    = threadIdx.x >> 5;
    const int band = blockIdx.x;
    const int b    = blockIdx.y >> 1;
    const int dir  = blockIdx.y & 1;
    const unsigned* ts = dir ? g_gmask : g_pmask;
    const unsigned* rs = dir ? g_pmask : g_gmask;

    const int r = band * MBAND + (w - 1) * 32 + lane;
    const bool valid    = ((unsigned)r < (unsigned)H);
    const bool interior = (w >= 1 && w <= MWARPS - 2);

    unsigned cur[16], unc[16];
    #pragma unroll
    for (int i = 0; i < 16; i++) { cur[i] = 0u; unc[i] = 0u; }
    if (valid) {
        const uint4* cp = reinterpret_cast<const uint4*>(rs + ((size_t)b * H + r) * WPR);
        #pragma unroll
        for (int j = 0; j < 4; j++) {
            uint4 c4 = cp[j];
            cur[4*j+0] = c4.x; cur[4*j+1] = c4.y; cur[4*j+2] = c4.z; cur[4*j+3] = c4.w;
        }
        if (interior) {
            const uint4* tp = reinterpret_cast<const uint4*>(ts + ((size_t)b * H + r) * WPR);
            #pragma unroll
            for (int j = 0; j < 4; j++) {
                uint4 t4 = tp[j];
                unc[4*j+0] = t4.x; unc[4*j+1] = t4.y; unc[4*j+2] = t4.z; unc[4*j+3] = t4.w;
            }
        }
    }

    int cnt = 0, notcov = 0;
    #pragma unroll
    for (int i = 0; i < 16; i++) cnt += __popc(unc[i]);

    __shared__ unsigned s_top[2][MWARPS][16];
    __shared__ unsigned s_bot[2][MWARPS][16];

    for (int d = 1; d <= 9; d++) {
        // horizontal dilation in place (rolling prev keeps original left word)
        unsigned prev = 0u;
        #pragma unroll
        for (int i = 0; i < 16; i++) {
            unsigned orig = cur[i];
            unsigned nxt  = (i < 15) ? cur[i + 1] : 0u;
            cur[i] = orig | (orig << 1) | (orig >> 1) | (prev >> 31) | (nxt << 31);
            prev = orig;
        }
        const int buf = d & 1;
        if (lane == 0) {
            #pragma unroll
            for (int i = 0; i < 16; i++) s_top[buf][w][i] = cur[i];
        }
        if (lane == 31) {
            #pragma unroll
            for (int i = 0; i < 16; i++) s_bot[buf][w][i] = cur[i];
        }
        __syncthreads();
        #pragma unroll
        for (int i = 0; i < 16; i++) {
            unsigned up = __shfl_up_sync(0xffffffffu, cur[i], 1);
            unsigned dn = __shfl_down_sync(0xffffffffu, cur[i], 1);
            if (lane == 0)  up = (w > 0) ? s_bot[buf][w - 1][i] : 0u;
            if (lane == 31) dn = (w < MWARPS - 1) ? s_top[buf][w + 1][i] : 0u;
            cur[i] |= up | dn;
        }
        #pragma unroll
        for (int i = 0; i < 16; i++) {
            unc[i] &= ~cur[i];
            notcov += __popc(unc[i]);
        }
    }

    // warp reduce
    #pragma unroll
    for (int o = 16; o; o >>= 1) {
        notcov += __shfl_down_sync(0xffffffffu, notcov, o);
        cnt    += __shfl_down_sync(0xffffffffu, cnt, o);
    }
    __shared__ int sred[MWARPS][2];
    if (lane == 0) { sred[w][0] = notcov; sred[w][1] = cnt; }
    __syncthreads();
    if (threadIdx.x == 0) {
        int N = 0, C = 0;
        #pragma unroll
        for (int i = 0; i < MWARPS; i++) { N += sred[i][0]; C += sred[i][1]; }
        g_mds [b][dir][band] = C + N;   // telescoped distance sum
        g_mcnt[b][dir][band] = C;
    }

    // ---- last-block finalize ----
    __shared__ bool isLast;
    __syncthreads();
    if (threadIdx.x == 0) {
        __threadfence();
        int old = atomicAdd(&g_done, 1);
        isLast = (old == MEDIAL_BLOCKS - 1);
    }
    __syncthreads();
    if (!isLast) return;
    __threadfence();

    __shared__ float acc[B][12];
    __shared__ float sd[B], ss[B], sm2[B];
    int t = threadIdx.x;
    for (int idx = t; idx < B * 12; idx += MTHREADS) {
        int bb = idx / 12, k = idx % 12;
        float s = 0.f;
        #pragma unroll
        for (int i = 0; i < GX; i++) s += g_part[i][bb][k];
        acc[bb][k] = s;
    }
    __syncthreads();

    if (t < B) {
        int bb = t;
        float inter = acc[bb][0], ps = acc[bb][1], gs = acc[bb][2];
        float dice = (2.f * inter + 1.f) / (ps + gs + 1.f);

        float pe = acc[bb][3],  ge = acc[bb][4],  ie = acc[bb][5];
        float pm = acc[bb][6],  gm = acc[bb][7],  im = acc[bb][8];
        float pj = acc[bb][9],  gj = acc[bb][10], ij = acc[bb][11];
        float e_iou = (ie + 1.f) / (pe + ge - ie + 1.f);
        float m_iou = (im + 1.f) / (pm + gm - im + 1.f);
        float j_iou = (ij + 1.f) / (pj + gj - ij + 1.f);
        float total = ge + gj + gm + 1.f;
        float sl = 1.f - ((ge / total) * e_iou + (gj / total) * j_iou + (gm / total) * m_iou);

        int ds0 = 0, ds1 = 0, c0 = 0, c1 = 0;
        #pragma unroll
        for (int i = 0; i < MNB; i++) {
            ds0 += g_mds[bb][0][i];  c0 += g_mcnt[bb][0][i];
            ds1 += g_mds[bb][1][i];  c1 += g_mcnt[bb][1][i];
        }
        float p2g = (float)ds0 / ((float)c0 + 1.f);
        float g2p = (float)ds1 / ((float)c1 + 1.f);
        float med = ((p2g + g2p) * 0.5f) / 10.f;

        sd[bb] = dice; ss[bb] = sl; sm2[bb] = med;
    }
    __syncthreads();

    if (t == 0) {
        float d = 0.f, s = 0.f, m = 0.f;
        for (int i = 0; i < B; i++) { d += sd[i]; s += ss[i]; m += sm2[i]; }
        d *= (1.f / B); s *= (1.f / B); m *= (1.f / B);
        float dl = 1.f - d;
        float avg = (dl + s + m) / 3.f;
        out[0] = dl / (dl + 1.f) * avg + s / (s + 1.f) * avg + m / (m + 1.f) * avg;
        g_done = 0;                              // reset for next graph replay
    }
}

extern "C" void kernel_launch(void* const* d_in, const int* in_sizes, int n_in,
                              void* d_out, int out_size) {
    const float* pred = (const float*)d_in[0];
    const float* gt   = (const float*)d_in[1];
    float* out = (float*)d_out;
    (void)in_sizes; (void)n_in; (void)out_size;

    stats_kernel<<<dim3(GX, B), 128>>>(pred, gt);
    medial_kernel<<<dim3(MNB, B * 2), MTHREADS>>>(out);
}

// round 8
// speedup vs baseline: 1.2259x; 1.2259x over previous
#include <cuda_runtime.h>

#define B 32
#define H 512
#define W 512
#define WPR 16                   // 512 bits / 32 = 16 words per row
#define STRIP 32                 // rows per warp (stats)
#define GX (H / STRIP)           // 16 stats row-blocks per batch

#define MINT 14                  // interior rows per medial warp (32 - 2*9 halo)
#define MWPB 4                   // medial warps per block
#define MGX 10                   // ceil(37 strips / 4) blocks in x
#define MEDIAL_BLOCKS (MGX * B * 2)

// ---- device scratch (no allocations allowed) ----
__device__ unsigned g_pmask[B * H * WPR];
__device__ unsigned g_gmask[B * H * WPR];
__device__ float    g_part[GX][B][12];   // per-CTA stats partials (race-free)
__device__ int      g_msum[B][2];        // medial distance sums  (atomic, reset in finalize)
__device__ int      g_mc  [B][2];        // medial target counts  (atomic, reset in finalize)
__device__ int      g_done = 0;          // last-block counter (self-resetting)

// ======================= stats (unchanged) =======================
struct Raw { float4 v; float eL, eR; };

__device__ __forceinline__ Raw load_raw(const float* __restrict__ rowptr,
                                        int lane, int x0, bool ok) {
    Raw r;
    if (ok) {
        r.v  = *(const float4*)rowptr;
        r.eL = (lane == 0  && x0 > 0)     ? __ldg(rowptr - 1) : 0.f;
        r.eR = (lane == 31 && x0 + 4 < W) ? __ldg(rowptr + 4) : 0.f;
    } else {
        r.v = make_float4(0.f, 0.f, 0.f, 0.f);
        r.eL = r.eR = 0.f;
    }
    return r;
}

struct RowH { float p[4]; float h[4]; };

__device__ __forceinline__ RowH convert(const Raw& r, int lane) {
    float Lp = __shfl_up_sync(0xffffffffu, r.v.w, 1);
    float Rp = __shfl_down_sync(0xffffffffu, r.v.x, 1);
    if (lane == 0)  Lp = r.eL;
    if (lane == 31) Rp = r.eR;
    RowH o;
    o.p[0] = r.v.x; o.p[1] = r.v.y; o.p[2] = r.v.z; o.p[3] = r.v.w;
    o.h[0] = Lp + r.v.x + r.v.y;
    o.h[1] = r.v.x + r.v.y + r.v.z;
    o.h[2] = r.v.y + r.v.z + r.v.w;
    o.h[3] = r.v.z + r.v.w + Rp;
    return o;
}

__global__ void __launch_bounds__(128) stats_kernel(const float* __restrict__ pred,
                                                    const float* __restrict__ gt) {
    const int lane = threadIdx.x & 31;
    const int cs   = threadIdx.x >> 5;
    const int b    = blockIdx.y;
    const int y0   = blockIdx.x * STRIP;
    const int x0   = cs * 128 + lane * 4;

    const float* Pp = pred + (size_t)b * H * W + x0 + (size_t)(y0 - 1) * W;
    const float* Gp = gt   + (size_t)b * H * W + x0 + (size_t)(y0 - 1) * W;

    Raw rp = load_raw(Pp, lane, x0, y0 > 0);
    Raw rg = load_raw(Gp, lane, x0, y0 > 0);
    Pp += W; Gp += W;
    Raw rp0 = load_raw(Pp, lane, x0, true);
    Raw rg0 = load_raw(Gp, lane, x0, true);
    Pp += W; Gp += W;
    Raw vP1 = load_raw(Pp, lane, x0, y0 + 1 < H);
    Raw vG1 = load_raw(Gp, lane, x0, y0 + 1 < H);
    Pp += W; Gp += W;
    Raw vP2 = load_raw(Pp, lane, x0, y0 + 2 < H);
    Raw vG2 = load_raw(Gp, lane, x0, y0 + 2 < H);
    Pp += W; Gp += W;
    Raw vP3 = load_raw(Pp, lane, x0, y0 + 3 < H);
    Raw vG3 = load_raw(Gp, lane, x0, y0 + 3 < H);
    Pp += W; Gp += W;

    RowH ppr = convert(rp, lane);
    RowH gpr = convert(rg, lane);
    float pph[4] = { ppr.h[0], ppr.h[1], ppr.h[2], ppr.h[3] };
    float gph[4] = { gpr.h[0], gpr.h[1], gpr.h[2], gpr.h[3] };
    RowH pc = convert(rp0, lane);
    RowH gc = convert(rg0, lane);

    float a_i = 0.f, a_p = 0.f, a_g = 0.f;
    int c[9] = {0, 0, 0, 0, 0, 0, 0, 0, 0};

    #pragma unroll 4
    for (int j = 0; j < STRIP; j++) {
        const int y = y0 + j;
        Raw vPn = load_raw(Pp, lane, x0, y + 4 < H);
        Raw vGn = load_raw(Gp, lane, x0, y + 4 < H);
        Pp += W; Gp += W;

        RowH pnx = convert(vP1, lane);
        RowH gnx = convert(vG1, lane);

        unsigned pnib = 0, gnib = 0;
        #pragma unroll
        for (int i = 0; i < 4; i++) {
            float pv = pc.p[i], gv = gc.p[i];
            float pn = pph[i] + pc.h[i] + pnx.h[i] - pv;
            float gn = gph[i] + gc.h[i] + gnx.h[i] - gv;
            bool pon = pv > 0.5f, gon = gv > 0.5f;
            int pe = pon && (pn == 1.f), pm = pon && (pn == 2.f), pj = pon && (pn > 2.f);
            int ge = gon && (gn == 1.f), gm = gon && (gn == 2.f), gj = gon && (gn > 2.f);
            a_i += pv * gv; a_p += pv; a_g += gv;
            c[0] += pe; c[1] += ge; c[2] += (pe & ge);
            c[3] += pm; c[4] += gm; c[5] += (pm & gm);
            c[6] += pj; c[7] += gj; c[8] += (pj & gj);
            pnib |= (unsigned)pon << i;
            gnib |= (unsigned)gon << i;
        }

        unsigned pw = pnib << ((lane & 7) * 4);
        unsigned gw = gnib << ((lane & 7) * 4);
        pw |= __shfl_xor_sync(0xffffffffu, pw, 1);
        gw |= __shfl_xor_sync(0xffffffffu, gw, 1);
        pw |= __shfl_xor_sync(0xffffffffu, pw, 2);
        gw |= __shfl_xor_sync(0xffffffffu, gw, 2);
        pw |= __shfl_xor_sync(0xffffffffu, pw, 4);
        gw |= __shfl_xor_sync(0xffffffffu, gw, 4);
        if ((lane & 7) == 0) {
            size_t widx = (size_t)(b * H + y) * WPR + cs * 4 + (lane >> 3);
            g_pmask[widx] = pw;
            g_gmask[widx] = gw;
        }

        #pragma unroll
        for (int i = 0; i < 4; i++) { pph[i] = pc.h[i]; gph[i] = gc.h[i]; }
        pc = pnx; gc = gnx;
        vP1 = vP2; vG1 = vG2;
        vP2 = vP3; vG2 = vG3;
        vP3 = vPn; vG3 = vGn;
    }

    #pragma unroll
    for (int o = 16; o; o >>= 1) {
        a_i += __shfl_down_sync(0xffffffffu, a_i, o);
        a_p += __shfl_down_sync(0xffffffffu, a_p, o);
        a_g += __shfl_down_sync(0xffffffffu, a_g, o);
    }
    #pragma unroll
    for (int k = 0; k < 9; k++) {
        #pragma unroll
        for (int o = 16; o; o >>= 1) c[k] += __shfl_down_sync(0xffffffffu, c[k], o);
    }

    __shared__ float sf[3];
    __shared__ int   si[9];
    if (threadIdx.x < 3) sf[threadIdx.x] = 0.f;
    if (threadIdx.x < 9) si[threadIdx.x] = 0;
    __syncthreads();
    if (lane == 0) {
        atomicAdd(&sf[0], a_i); atomicAdd(&sf[1], a_p); atomicAdd(&sf[2], a_g);
        #pragma unroll
        for (int k = 0; k < 9; k++) atomicAdd(&si[k], c[k]);
    }
    __syncthreads();
    if (threadIdx.x < 3)  g_part[blockIdx.x][b][threadIdx.x] = sf[threadIdx.x];
    if (threadIdx.x >= 3 && threadIdx.x < 12)
        g_part[blockIdx.x][b][threadIdx.x] = (float)si[threadIdx.x - 3];
}

// ======================= medial: warp-autonomous, barrier-free =======================
// grid (MGX, B*2), block 128 = 4 warps. Each warp owns 32 rows (lane = row),
// of which the middle MINT=14 are interior; 9-row halo each side makes all 9
// dilation rounds exact on interior lanes with ZERO inter-warp communication.
//   dist_sum = popc(tgt) + sum_{d=1..9} popc(unc_d),  unc_d = unc_{d-1} & ~dil_d
__global__ void __launch_bounds__(128, 6) medial_kernel(float* __restrict__ out) {
    const int lane  = threadIdx.x & 31;
    const int wid   = threadIdx.x >> 5;
    const int strip = blockIdx.x * MWPB + wid;   // 0..39 (37 useful)
    const int b     = blockIdx.y >> 1;
    const int dir   = blockIdx.y & 1;
    const unsigned* ts = dir ? g_gmask : g_pmask;
    const unsigned* rs = dir ? g_pmask : g_gmask;

    const int r = strip * MINT - 9 + lane;       // global row for this lane
    const bool valid    = ((unsigned)r < (unsigned)H);
    const bool interior = (lane >= 9) && (lane < 9 + MINT);

    unsigned cur[16], unc[16];
    #pragma unroll
    for (int i = 0; i < 16; i++) { cur[i] = 0u; unc[i] = 0u; }
    if (valid) {
        const uint4* cp = reinterpret_cast<const uint4*>(rs + ((size_t)b * H + r) * WPR);
        #pragma unroll
        for (int j = 0; j < 4; j++) {
            uint4 c4 = cp[j];
            cur[4*j+0] = c4.x; cur[4*j+1] = c4.y; cur[4*j+2] = c4.z; cur[4*j+3] = c4.w;
        }
        if (interior) {
            const uint4* tp = reinterpret_cast<const uint4*>(ts + ((size_t)b * H + r) * WPR);
            #pragma unroll
            for (int j = 0; j < 4; j++) {
                uint4 t4 = tp[j];
                unc[4*j+0] = t4.x; unc[4*j+1] = t4.y; unc[4*j+2] = t4.z; unc[4*j+3] = t4.w;
            }
        }
    }

    int cnt = 0, notcov = 0;
    #pragma unroll
    for (int i = 0; i < 16; i++) cnt += __popc(unc[i]);

    #pragma unroll
    for (int d = 1; d <= 9; d++) {
        // horizontal dilation in place (rolling prev keeps original left word)
        unsigned prev = 0u;
        #pragma unroll
        for (int i = 0; i < 16; i++) {
            unsigned orig = cur[i];
            unsigned nxt  = (i < 15) ? cur[i + 1] : 0u;
            cur[i] = orig | (orig << 1) | (orig >> 1) | (prev >> 31) | (nxt << 31);
            prev = orig;
        }
        // vertical dilation: pure intra-warp shuffles, branchless edge zeroing
        #pragma unroll
        for (int i = 0; i < 16; i++) {
            unsigned up = __shfl_up_sync(0xffffffffu, cur[i], 1);
            unsigned dn = __shfl_down_sync(0xffffffffu, cur[i], 1);
            up = (lane == 0)  ? 0u : up;
            dn = (lane == 31) ? 0u : dn;
            cur[i] |= up | dn;
        }
        // uncovered-set shrink + telescoped distance accumulation
        #pragma unroll
        for (int i = 0; i < 16; i++) {
            unc[i] &= ~cur[i];
            notcov += __popc(unc[i]);
        }
    }

    // warp reduce, then 2 integer atomics per warp (REDG, low contention)
    int dist = cnt + notcov;
    #pragma unroll
    for (int o = 16; o; o >>= 1) {
        dist += __shfl_down_sync(0xffffffffu, dist, o);
        cnt  += __shfl_down_sync(0xffffffffu, cnt, o);
    }
    if (lane == 0 && dist != 0) atomicAdd(&g_msum[b][dir], dist);
    if (lane == 0 && cnt  != 0) atomicAdd(&g_mc[b][dir], cnt);

    // ---- last-block finalize ----
    __shared__ bool isLast;
    __syncthreads();
    if (threadIdx.x == 0) {
        __threadfence();
        int old = atomicAdd(&g_done, 1);
        isLast = (old == MEDIAL_BLOCKS - 1);
    }
    __syncthreads();
    if (!isLast) return;
    __threadfence();

    __shared__ float acc[B][12];
    __shared__ float sd[B], ss[B], sm2[B];
    int t = threadIdx.x;
    for (int idx = t; idx < B * 12; idx += 128) {
        int bb = idx / 12, k = idx % 12;
        float s = 0.f;
        #pragma unroll
        for (int i = 0; i < GX; i++) s += g_part[i][bb][k];
        acc[bb][k] = s;
    }
    __syncthreads();

    if (t < B) {
        int bb = t;
        float inter = acc[bb][0], ps = acc[bb][1], gs = acc[bb][2];
        float dice = (2.f * inter + 1.f) / (ps + gs + 1.f);

        float pe = acc[bb][3],  ge = acc[bb][4],  ie = acc[bb][5];
        float pm = acc[bb][6],  gm = acc[bb][7],  im = acc[bb][8];
        float pj = acc[bb][9],  gj = acc[bb][10], ij = acc[bb][11];
        float e_iou = (ie + 1.f) / (pe + ge - ie + 1.f);
        float m_iou = (im + 1.f) / (pm + gm - im + 1.f);
        float j_iou = (ij + 1.f) / (pj + gj - ij + 1.f);
        float total = ge + gj + gm + 1.f;
        float sl = 1.f - ((ge / total) * e_iou + (gj / total) * j_iou + (gm / total) * m_iou);

        float p2g = (float)g_msum[bb][0] / ((float)g_mc[bb][0] + 1.f);
        float g2p = (float)g_msum[bb][1] / ((float)g_mc[bb][1] + 1.f);
        float med = ((p2g + g2p) * 0.5f) / 10.f;

        sd[bb] = dice; ss[bb] = sl; sm2[bb] = med;
    }
    __syncthreads();

    // reset accumulators for the next graph replay
    if (t < B * 2) {
        ((int*)g_msum)[t] = 0;
        ((int*)g_mc)[t]   = 0;
    }

    if (t == 0) {
        float d = 0.f, s = 0.f, m = 0.f;
        for (int i = 0; i < B; i++) { d += sd[i]; s += ss[i]; m += sm2[i]; }
        d *= (1.f / B); s *= (1.f / B); m *= (1.f / B);
        float dl = 1.f - d;
        float avg = (dl + s + m) / 3.f;
        out[0] = dl / (dl + 1.f) * avg + s / (s + 1.f) * avg + m / (m + 1.f) * avg;
        g_done = 0;                              // reset for next graph replay
    }
}

extern "C" void kernel_launch(void* const* d_in, const int* in_sizes, int n_in,
                              void* d_out, int out_size) {
    const float* pred = (const float*)d_in[0];
    const float* gt   = (const float*)d_in[1];
    float* out = (float*)d_out;
    (void)in_sizes; (void)n_in; (void)out_size;

    stats_kernel<<<dim3(GX, B), 128>>>(pred, gt);
    medial_kernel<<<dim3(MGX, B * 2), 128>>>(out);
}